// round 12
// baseline (speedup 1.0000x reference)
#include <cuda_runtime.h>
#include <cuda_bf16.h>
#include <cfloat>
#include <cstdint>

namespace {
constexpr int kB  = 2;
constexpr int kH  = 8;
constexpr int kS  = 2048;
constexpr int kDK = 32;
constexpr int kDM = 256;
constexpr int kNRow = kB * kS;           // 4096
constexpr float kScale = 0.17677669529663687f;  // 1/sqrt(32)
constexpr int kCap = 128;                // candidate cap per query row
constexpr int kKC  = 64;                 // cat K: [hi(32) | lo(32)] bf16
constexpr int kNT  = kS / 128;           // 16 column tiles per row
constexpr int kRows = kB * kH * kS;      // 32768 query rows
constexpr float kThrMargin = 1.0625f;    // 1 + hi-only max error bound
}

// Scratch buffers.
__device__ float g_v[kB * kH * kS * kDK];                 // V fp32
__device__ __nv_bfloat16 g_qcat[kB * kH * kS * kKC];      // [Qhi*scale | Qlo*scale]
__device__ __nv_bfloat16 g_kcat[kB * kH * kS * kKC];      // [Khi | Klo]
__device__ float g_tilemax[(size_t)kRows * kNT];          // per-row per-tile max (hi-only)
__device__ float g_thr[kRows];                            // per-row threshold
__device__ unsigned g_cnt[kRows];                         // per-row candidate count
__device__ float2 g_cand[(size_t)kRows * kCap];           // candidate (value, col)

// ---------------------------------------------------------------------------
// Helpers
// ---------------------------------------------------------------------------
__device__ __forceinline__ uint32_t smem_u32(const void* p) {
    uint32_t a;
    asm("{ .reg .u64 t; cvta.to.shared.u64 t, %1; cvt.u32.u64 %0, t; }"
        : "=r"(a) : "l"(p));
    return a;
}
__device__ __forceinline__ void ldsm_x4(uint32_t* r, uint32_t addr) {
    asm volatile("ldmatrix.sync.aligned.m8n8.x4.shared.b16 {%0,%1,%2,%3}, [%4];"
                 : "=r"(r[0]), "=r"(r[1]), "=r"(r[2]), "=r"(r[3]) : "r"(addr));
}
__device__ __forceinline__ void mma_bf16(float* d, const uint32_t* a, const uint32_t* b) {
    asm volatile(
        "mma.sync.aligned.m16n8k16.row.col.f32.bf16.bf16.f32 "
        "{%0,%1,%2,%3}, {%4,%5,%6,%7}, {%8,%9}, {%0,%1,%2,%3};"
        : "+f"(d[0]), "+f"(d[1]), "+f"(d[2]), "+f"(d[3])
        : "r"(a[0]), "r"(a[1]), "r"(a[2]), "r"(a[3]), "r"(b[0]), "r"(b[1]));
}
#define SW128(off) ((off) ^ (((off) >> 3) & 0x70))

// ---------------------------------------------------------------------------
// Kernel 1 — projection GEMM; epilogue emits V fp32 and bf16 hi/lo cat
// buffers (Q pre-scaled by 1/sqrt(dk)).
// ---------------------------------------------------------------------------
__global__ __launch_bounds__(256)
void proj_kernel(const float* __restrict__ xq, const float* __restrict__ xk,
                 const float* __restrict__ xv,
                 const float* __restrict__ wq, const float* __restrict__ bq,
                 const float* __restrict__ wk, const float* __restrict__ bk,
                 const float* __restrict__ wv, const float* __restrict__ bv)
{
    constexpr int PBM = 128, PBN = 64, PBK = 16;
    __shared__ float As[PBK][PBM];
    __shared__ float Bs[PBK][PBN];

    const int z = blockIdx.z;
    const float* __restrict__ X    = (z == 0) ? xq : (z == 1) ? xk : xv;
    const float* __restrict__ W    = (z == 0) ? wq : (z == 1) ? wk : wv;
    const float* __restrict__ bias = (z == 0) ? bq : (z == 1) ? bk : bv;

    const int n0 = blockIdx.y * PBM;
    const int c0 = blockIdx.x * PBN;
    const int tid = threadIdx.x;
    const int tx = tid & 15;
    const int ty = tid >> 4;

    float acc[8][4];
    #pragma unroll
    for (int i = 0; i < 8; ++i)
        #pragma unroll
        for (int j = 0; j < 4; ++j) acc[i][j] = 0.0f;

    for (int k0 = 0; k0 < kDM; k0 += PBK) {
        #pragma unroll
        for (int r = 0; r < 2; ++r) {
            int f   = tid + r * 256;
            int row = f >> 2;
            int kk  = (f & 3) * 4;
            float4 v = *reinterpret_cast<const float4*>(X + (n0 + row) * kDM + k0 + kk);
            As[kk + 0][row] = v.x; As[kk + 1][row] = v.y;
            As[kk + 2][row] = v.z; As[kk + 3][row] = v.w;
        }
        {
            int n  = tid >> 2;
            int kk = (tid & 3) * 4;
            float4 v = *reinterpret_cast<const float4*>(W + (c0 + n) * kDM + k0 + kk);
            Bs[kk + 0][n] = v.x; Bs[kk + 1][n] = v.y;
            Bs[kk + 2][n] = v.z; Bs[kk + 3][n] = v.w;
        }
        __syncthreads();

        #pragma unroll
        for (int k = 0; k < PBK; ++k) {
            float4 a0 = *reinterpret_cast<const float4*>(&As[k][ty * 8]);
            float4 a1 = *reinterpret_cast<const float4*>(&As[k][ty * 8 + 4]);
            float4 bb = *reinterpret_cast<const float4*>(&Bs[k][tx * 4]);
            float a[8] = {a0.x, a0.y, a0.z, a0.w, a1.x, a1.y, a1.z, a1.w};
            float b[4] = {bb.x, bb.y, bb.z, bb.w};
            #pragma unroll
            for (int i = 0; i < 8; ++i)
                #pragma unroll
                for (int j = 0; j < 4; ++j)
                    acc[i][j] = fmaf(a[i], b[j], acc[i][j]);
        }
        __syncthreads();
    }

    #pragma unroll
    for (int i = 0; i < 8; ++i) {
        const int row = n0 + ty * 8 + i;
        const int bb  = row / kS;
        const int ss  = row % kS;
        #pragma unroll
        for (int j = 0; j < 4; ++j) {
            const int col = c0 + tx * 4 + j;
            const int h = col >> 5, d = col & 31;
            const int r = (bb * kH + h) * kS + ss;
            float val = acc[i][j] + bias[col];
            if (z == 2) {
                g_v[r * kDK + d] = val;
            } else {
                if (z == 0) val *= kScale;           // pre-scale Q
                __nv_bfloat16 hi = __float2bfloat16(val);
                __nv_bfloat16 lo = __float2bfloat16(val - __bfloat162float(hi));
                __nv_bfloat16* dst = (z == 0) ? g_qcat : g_kcat;
                dst[r * kKC + d]       = hi;
                dst[r * kKC + 32 + d]  = lo;
            }
        }
    }
}

// ---------------------------------------------------------------------------
// Kernel 2a — scoreA: hi.hi-only HMMA GEMM; writes per-tile row maxes ONLY.
// ---------------------------------------------------------------------------
__global__ __launch_bounds__(256, 2)
void score_max_tc(void)
{
    __shared__ __align__(128) char sA[128 * 128];
    __shared__ __align__(128) char sB[128 * 128];
    __shared__ float sTmax[128][2];

    const int bh = blockIdx.z;
    const int i0 = blockIdx.y * 128;
    const int j0 = blockIdx.x * 128;
    const int tid  = threadIdx.x;
    const int wid  = tid >> 5;
    const int lane = tid & 31;

    const uint32_t sAu = smem_u32(sA);
    const uint32_t sBu = smem_u32(sB);

    {
        const uint4* __restrict__ Ag = reinterpret_cast<const uint4*>(
            g_qcat + ((size_t)bh * kS + i0) * kKC);
        const uint4* __restrict__ Bg = reinterpret_cast<const uint4*>(
            g_kcat + ((size_t)bh * kS + j0) * kKC);
        #pragma unroll
        for (int r = 0; r < 4; ++r) {
            const int f   = tid + r * 256;
            const int row = f >> 3;
            const int c16 = f & 7;
            const uint32_t off = SW128((uint32_t)(row * 128 + c16 * 16));
            *reinterpret_cast<uint4*>(sA + off) = Ag[row * 8 + c16];
            *reinterpret_cast<uint4*>(sB + off) = Bg[row * 8 + c16];
        }
    }
    __syncthreads();

    const int wm = wid & 3;
    const int wn = wid >> 2;
    const int imb = wm * 32;
    const int jnb = wn * 64;

    float acc[2][8][4];
    #pragma unroll
    for (int mt = 0; mt < 2; ++mt)
        #pragma unroll
        for (int nt = 0; nt < 8; ++nt)
            #pragma unroll
            for (int e = 0; e < 4; ++e) acc[mt][nt][e] = 0.0f;

    // hi.hi only: k chunks 0,16 (first 64 B of each row)
    #pragma unroll
    for (int kk = 0; kk < 32; kk += 16) {
        uint32_t af[2][4];
        #pragma unroll
        for (int mt = 0; mt < 2; ++mt) {
            const int row = imb + mt * 16 + (lane & 15);
            const int chk = (kk >> 3) + (lane >> 4);
            ldsm_x4(af[mt], sAu + SW128((uint32_t)(row * 128 + chk * 16)));
        }
        uint32_t bf[8][2];
        #pragma unroll
        for (int np = 0; np < 4; ++np) {
            const int row = jnb + np * 16 + (lane & 7) + ((lane & 16) >> 1);
            const int chk = (kk >> 3) + ((lane >> 3) & 1);
            uint32_t r4[4];
            ldsm_x4(r4, sBu + SW128((uint32_t)(row * 128 + chk * 16)));
            bf[np * 2 + 0][0] = r4[0]; bf[np * 2 + 0][1] = r4[1];
            bf[np * 2 + 1][0] = r4[2]; bf[np * 2 + 1][1] = r4[3];
        }
        #pragma unroll
        for (int mt = 0; mt < 2; ++mt)
            #pragma unroll
            for (int nt = 0; nt < 8; ++nt)
                mma_bf16(acc[mt][nt], af[mt], bf[nt]);
    }

    const int g  = lane >> 2;
    const int tg = lane & 3;
    #pragma unroll
    for (int mt = 0; mt < 2; ++mt) {
        const int r0 = imb + mt * 16 + g;
        float rm0 = -FLT_MAX, rm1 = -FLT_MAX;
        #pragma unroll
        for (int nt = 0; nt < 8; ++nt) {
            rm0 = fmaxf(rm0, fmaxf(acc[mt][nt][0], acc[mt][nt][1]));
            rm1 = fmaxf(rm1, fmaxf(acc[mt][nt][2], acc[mt][nt][3]));
        }
        rm0 = fmaxf(rm0, __shfl_xor_sync(0xffffffffu, rm0, 1));
        rm0 = fmaxf(rm0, __shfl_xor_sync(0xffffffffu, rm0, 2));
        rm1 = fmaxf(rm1, __shfl_xor_sync(0xffffffffu, rm1, 1));
        rm1 = fmaxf(rm1, __shfl_xor_sync(0xffffffffu, rm1, 2));
        if (tg == 0) {
            sTmax[r0][wn]     = rm0;
            sTmax[r0 + 8][wn] = rm1;
        }
    }
    __syncthreads();
    if (tid < 128) {
        g_tilemax[((size_t)bh * kS + i0 + tid) * kNT + blockIdx.x] =
            fmaxf(sTmax[tid][0], sTmax[tid][1]);
    }
}

// ---------------------------------------------------------------------------
// Kernel 2b — rowmax reduce: thr = rowmax(hi-only) - margin; zero counters.
// ---------------------------------------------------------------------------
__global__ __launch_bounds__(256)
void rowmax_kernel(void)
{
    const int r = blockIdx.x * 256 + threadIdx.x;
    const float* __restrict__ tm = g_tilemax + (size_t)r * kNT;
    float m = -FLT_MAX;
    #pragma unroll
    for (int t = 0; t < kNT; ++t) m = fmaxf(m, __ldg(tm + t));
    g_thr[r] = m - kThrMargin;
    g_cnt[r] = 0u;
}

// ---------------------------------------------------------------------------
// Kernel 2c — scoreB: full 3-product HMMA GEMM; epilogue appends candidates
// (s > thr[row]) to per-row gmem lists via atomicAdd. No dense score store.
// ---------------------------------------------------------------------------
__global__ __launch_bounds__(256, 2)
void score_compact_tc(void)
{
    __shared__ __align__(128) char sA[128 * 128];
    __shared__ __align__(128) char sB[128 * 128];

    const int bh = blockIdx.z;
    const int i0 = blockIdx.y * 128;
    const int j0 = blockIdx.x * 128;
    const int tid  = threadIdx.x;
    const int wid  = tid >> 5;
    const int lane = tid & 31;

    const uint32_t sAu = smem_u32(sA);
    const uint32_t sBu = smem_u32(sB);

    {
        const uint4* __restrict__ Ag = reinterpret_cast<const uint4*>(
            g_qcat + ((size_t)bh * kS + i0) * kKC);
        const uint4* __restrict__ Bg = reinterpret_cast<const uint4*>(
            g_kcat + ((size_t)bh * kS + j0) * kKC);
        #pragma unroll
        for (int r = 0; r < 4; ++r) {
            const int f   = tid + r * 256;
            const int row = f >> 3;
            const int c16 = f & 7;
            const uint32_t off = SW128((uint32_t)(row * 128 + c16 * 16));
            *reinterpret_cast<uint4*>(sA + off) = Ag[row * 8 + c16];
            *reinterpret_cast<uint4*>(sB + off) = Bg[row * 8 + c16];
        }
    }
    __syncthreads();

    const int wm = wid & 3;
    const int wn = wid >> 2;
    const int imb = wm * 32;
    const int jnb = wn * 64;

    float acc[2][8][4];
    #pragma unroll
    for (int mt = 0; mt < 2; ++mt)
        #pragma unroll
        for (int nt = 0; nt < 8; ++nt)
            #pragma unroll
            for (int e = 0; e < 4; ++e) acc[mt][nt][e] = 0.0f;

    const int aoff[3] = {0, 32, 0};
    const int boff[3] = {0, 0, 32};
    #pragma unroll
    for (int p = 0; p < 3; ++p) {
        #pragma unroll
        for (int kk = 0; kk < 32; kk += 16) {
            const int kcA = aoff[p] + kk;
            const int kcB = boff[p] + kk;

            uint32_t af[2][4];
            #pragma unroll
            for (int mt = 0; mt < 2; ++mt) {
                const int row = imb + mt * 16 + (lane & 15);
                const int chk = (kcA >> 3) + (lane >> 4);
                ldsm_x4(af[mt], sAu + SW128((uint32_t)(row * 128 + chk * 16)));
            }
            uint32_t bf[8][2];
            #pragma unroll
            for (int np = 0; np < 4; ++np) {
                const int row = jnb + np * 16 + (lane & 7) + ((lane & 16) >> 1);
                const int chk = (kcB >> 3) + ((lane >> 3) & 1);
                uint32_t r4[4];
                ldsm_x4(r4, sBu + SW128((uint32_t)(row * 128 + chk * 16)));
                bf[np * 2 + 0][0] = r4[0]; bf[np * 2 + 0][1] = r4[1];
                bf[np * 2 + 1][0] = r4[2]; bf[np * 2 + 1][1] = r4[3];
            }
            #pragma unroll
            for (int mt = 0; mt < 2; ++mt)
                #pragma unroll
                for (int nt = 0; nt < 8; ++nt)
                    mma_bf16(acc[mt][nt], af[mt], bf[nt]);
        }
    }

    // Epilogue: candidate append (s > thr[row]).
    const int g  = lane >> 2;
    const int tg = lane & 3;
    #pragma unroll
    for (int mt = 0; mt < 2; ++mt) {
        const size_t rowg0 = (size_t)bh * kS + i0 + imb + mt * 16 + g;
        const float thr0 = __ldg(g_thr + rowg0);
        const float thr1 = __ldg(g_thr + rowg0 + 8);
        #pragma unroll
        for (int nt = 0; nt < 8; ++nt) {
            const int colb = j0 + jnb + nt * 8 + tg * 2;
            #pragma unroll
            for (int e = 0; e < 4; ++e) {
                const float v = acc[mt][nt][e];
                const size_t rowg = (e < 2) ? rowg0 : rowg0 + 8;
                const float thr  = (e < 2) ? thr0 : thr1;
                if (v > thr) {
                    unsigned idx = atomicAdd(&g_cnt[rowg], 1u);
                    if (idx < (unsigned)kCap)
                        g_cand[rowg * kCap + idx] =
                            make_float2(v, __int_as_float(colb + (e & 1)));
                }
            }
        }
    }
}

// ---------------------------------------------------------------------------
// Exact slow fallback (candidate overflow; ~never): recompute row scores
// from qcat/kcat in fp32 (hi+lo), Michelot + ballot-pop AV.
// ---------------------------------------------------------------------------
__device__ __noinline__ float slow_row(size_t rowg, int bh, float tau0,
                                       const float* __restrict__ Vbh, int lane)
{
    const __nv_bfloat16* __restrict__ Qr = g_qcat + rowg * kKC;
    const __nv_bfloat16* __restrict__ Kb = g_kcat + (size_t)bh * kS * kKC;
    float q[kDK];
    #pragma unroll
    for (int d = 0; d < kDK; ++d)
        q[d] = __bfloat162float(Qr[d]) + __bfloat162float(Qr[32 + d]);

    float tau = tau0;
    int prev = -1;
    for (int it = 0; it < 200; ++it) {
        float sum = 0.0f; int c = 0;
        for (int j = lane; j < kS; j += 32) {
            const __nv_bfloat16* kr = Kb + (size_t)j * kKC;
            float s = 0.0f;
            #pragma unroll
            for (int d = 0; d < kDK; ++d)
                s = fmaf(q[d], __bfloat162float(kr[d]) + __bfloat162float(kr[32 + d]), s);
            if (s > tau) { sum += s; ++c; }
        }
        #pragma unroll
        for (int o = 16; o; o >>= 1) {
            sum += __shfl_xor_sync(0xffffffffu, sum, o);
            c   += __shfl_xor_sync(0xffffffffu, c, o);
        }
        if (c == prev || c == 0) break;
        tau = (sum - 1.0f) / (float)c;
        prev = c;
    }
    float a = 0.0f;
    for (int j = lane; j < kS; j += 32) {
        const __nv_bfloat16* kr = Kb + (size_t)j * kKC;
        float s = 0.0f;
        #pragma unroll
        for (int d = 0; d < kDK; ++d)
            s = fmaf(q[d], __bfloat162float(kr[d]) + __bfloat162float(kr[32 + d]), s);
        float w = s - tau;
        unsigned mk = __ballot_sync(0xffffffffu, w > 0.0f);
        while (mk) {
            int b = __ffs(mk) - 1;
            mk &= mk - 1;
            float wb = __shfl_sync(0xffffffffu, w, b);
            int jj = __shfl_sync(0xffffffffu, j, b);
            a = fmaf(wb, __ldg(Vbh + jj * kDK + lane), a);
        }
    }
    return a;
}

// ---------------------------------------------------------------------------
// Kernel 3 — finalize: per-warp per-row Michelot on gmem candidate list + AV.
// ---------------------------------------------------------------------------
__global__ __launch_bounds__(256, 2)
void finalize_av(float* __restrict__ out)
{
    __shared__ float2 Lists[8][kCap];

    const int bh   = blockIdx.y;
    const int warp = threadIdx.x >> 5;
    const int lane = threadIdx.x & 31;
    const int qi   = blockIdx.x * 8 + warp;
    const size_t rowg = (size_t)bh * kS + qi;

    const float* __restrict__ Vbh = g_v + bh * kS * kDK;
    const float thr = __ldg(g_thr + rowg);
    const int n = (int)__ldg(g_cnt + rowg);

    float a;
    if (n <= kCap) {
        // Copy candidates to smem (coalesced within warp)
        float2* __restrict__ Lq = Lists[warp];
        const float2* __restrict__ Gq = g_cand + rowg * kCap;
        #pragma unroll
        for (int r = 0; r < 4; ++r) {
            const int i = r * 32 + lane;
            if (i < n) Lq[i] = __ldg(Gq + i);
        }
        __syncwarp();

        float c0 = (lane      < n) ? Lq[lane     ].x : -FLT_MAX;
        float c1 = (lane + 32 < n) ? Lq[lane + 32].x : -FLT_MAX;
        float c2 = (lane + 64 < n) ? Lq[lane + 64].x : -FLT_MAX;
        float c3 = (lane + 96 < n) ? Lq[lane + 96].x : -FLT_MAX;
        float tau = thr;
        int prev = -1;
        for (int it = 0; it < 80; ++it) {
            float sum = 0.0f; int cnt = 0;
            if (c0 > tau) { sum += c0; ++cnt; }
            if (c1 > tau) { sum += c1; ++cnt; }
            if (c2 > tau) { sum += c2; ++cnt; }
            if (c3 > tau) { sum += c3; ++cnt; }
            #pragma unroll
            for (int o = 16; o; o >>= 1) {
                sum += __shfl_xor_sync(0xffffffffu, sum, o);
                cnt += __shfl_xor_sync(0xffffffffu, cnt, o);
            }
            if (cnt == prev || cnt == 0) break;
            tau = (sum - 1.0f) / (float)cnt;
            prev = cnt;
        }
        float a0 = 0.0f, a1 = 0.0f;
        int ci = 0;
        for (; ci + 2 <= n; ci += 2) {
            float2 p0 = Lq[ci], p1 = Lq[ci + 1];
            float w0 = fmaxf(p0.x - tau, 0.0f);
            float w1 = fmaxf(p1.x - tau, 0.0f);
            a0 = fmaf(w0, __ldg(Vbh + __float_as_int(p0.y) * kDK + lane), a0);
            a1 = fmaf(w1, __ldg(Vbh + __float_as_int(p1.y) * kDK + lane), a1);
        }
        if (ci < n) {
            float2 p = Lq[ci];
            float w = fmaxf(p.x - tau, 0.0f);
            a0 = fmaf(w, __ldg(Vbh + __float_as_int(p.y) * kDK + lane), a0);
        }
        a = a0 + a1;
    } else {
        a = slow_row(rowg, bh, thr, Vbh, lane);
    }

    const int bb = bh >> 3;
    const int h  = bh & 7;
    out[(bb * kS + qi) * kDM + h * kDK + lane] = a;
}

// ---------------------------------------------------------------------------
extern "C" void kernel_launch(void* const* d_in, const int* in_sizes, int n_in,
                              void* d_out, int out_size)
{
    const float* query = (const float*)d_in[0];
    const float* key   = (const float*)d_in[1];
    const float* value = (const float*)d_in[2];
    const float* Wq    = (const float*)d_in[3];
    const float* bq    = (const float*)d_in[4];
    const float* Wk    = (const float*)d_in[5];
    const float* bk    = (const float*)d_in[6];
    const float* Wv    = (const float*)d_in[7];
    const float* bv    = (const float*)d_in[8];
    float* out = (float*)d_out;

    dim3 pgrid(kDM / 64, kNRow / 128, 3);      // (4, 32, 3)
    proj_kernel<<<pgrid, 256>>>(query, key, value, Wq, bq, Wk, bk, Wv, bv);

    dim3 sgrid(kS / 128, kS / 128, kB * kH);   // (16, 16, 16)
    score_max_tc<<<sgrid, 256>>>();

    rowmax_kernel<<<kRows / 256, 256>>>();

    score_compact_tc<<<sgrid, 256>>>();

    dim3 agrid(kS / 8, kB * kH);               // (256, 16)
    finalize_av<<<agrid, 256>>>(out);

    (void)in_sizes; (void)n_in; (void)out_size;
}

// round 13
// speedup vs baseline: 7.2797x; 7.2797x over previous
#include <cuda_runtime.h>
#include <cuda_bf16.h>
#include <cfloat>
#include <cstdint>

namespace {
constexpr int kB  = 2;
constexpr int kH  = 8;
constexpr int kS  = 2048;
constexpr int kDK = 32;
constexpr int kDM = 256;
constexpr int kNRow = kB * kS;           // 4096
constexpr float kScale = 0.17677669529663687f;  // 1/sqrt(32)
constexpr int kCap = 128;                // candidate cap per query row
constexpr int kKC  = 64;                 // cat K: [hi(32) | lo(32)] bf16
constexpr int kJT  = 64;                 // score CTA j-tile
constexpr int kNT  = kS / kJT;           // 32 column tiles per row
}

// Scratch buffers.
__device__ float g_v[kB * kH * kS * kDK];                 // V fp32
__device__ __nv_bfloat16 g_qcat[kB * kH * kS * kKC];      // [Qhi*scale | Qlo*scale]
__device__ __nv_bfloat16 g_kcat[kB * kH * kS * kKC];      // [Khi | Klo]
__device__ float g_s[(size_t)kB * kH * kS * kS];          // scores (256 MiB)
__device__ float g_tilemax[(size_t)kB * kH * kS * kNT];   // per-row per-tile max (exact)

// ---------------------------------------------------------------------------
// Helpers
// ---------------------------------------------------------------------------
__device__ __forceinline__ uint32_t smem_u32(const void* p) {
    uint32_t a;
    asm("{ .reg .u64 t; cvta.to.shared.u64 t, %1; cvt.u32.u64 %0, t; }"
        : "=r"(a) : "l"(p));
    return a;
}
__device__ __forceinline__ void ldsm_x4(uint32_t* r, uint32_t addr) {
    asm volatile("ldmatrix.sync.aligned.m8n8.x4.shared.b16 {%0,%1,%2,%3}, [%4];"
                 : "=r"(r[0]), "=r"(r[1]), "=r"(r[2]), "=r"(r[3]) : "r"(addr));
}
__device__ __forceinline__ void mma_bf16(float* d, const uint32_t* a, const uint32_t* b) {
    asm volatile(
        "mma.sync.aligned.m16n8k16.row.col.f32.bf16.bf16.f32 "
        "{%0,%1,%2,%3}, {%4,%5,%6,%7}, {%8,%9}, {%0,%1,%2,%3};"
        : "+f"(d[0]), "+f"(d[1]), "+f"(d[2]), "+f"(d[3])
        : "r"(a[0]), "r"(a[1]), "r"(a[2]), "r"(a[3]), "r"(b[0]), "r"(b[1]));
}
#define SW128(off) ((off) ^ (((off) >> 3) & 0x70))

// ---------------------------------------------------------------------------
// Kernel 1 — projection GEMM; epilogue emits V fp32 and bf16 hi/lo cat
// buffers (Q pre-scaled by 1/sqrt(dk)).
// ---------------------------------------------------------------------------
__global__ __launch_bounds__(256)
void proj_kernel(const float* __restrict__ xq, const float* __restrict__ xk,
                 const float* __restrict__ xv,
                 const float* __restrict__ wq, const float* __restrict__ bq,
                 const float* __restrict__ wk, const float* __restrict__ bk,
                 const float* __restrict__ wv, const float* __restrict__ bv)
{
    constexpr int PBM = 128, PBN = 64, PBK = 16;
    __shared__ float As[PBK][PBM];
    __shared__ float Bs[PBK][PBN];

    const int z = blockIdx.z;
    const float* __restrict__ X    = (z == 0) ? xq : (z == 1) ? xk : xv;
    const float* __restrict__ W    = (z == 0) ? wq : (z == 1) ? wk : wv;
    const float* __restrict__ bias = (z == 0) ? bq : (z == 1) ? bk : bv;

    const int n0 = blockIdx.y * PBM;
    const int c0 = blockIdx.x * PBN;
    const int tid = threadIdx.x;
    const int tx = tid & 15;
    const int ty = tid >> 4;

    float acc[8][4];
    #pragma unroll
    for (int i = 0; i < 8; ++i)
        #pragma unroll
        for (int j = 0; j < 4; ++j) acc[i][j] = 0.0f;

    for (int k0 = 0; k0 < kDM; k0 += PBK) {
        #pragma unroll
        for (int r = 0; r < 2; ++r) {
            int f   = tid + r * 256;
            int row = f >> 2;
            int kk  = (f & 3) * 4;
            float4 v = *reinterpret_cast<const float4*>(X + (n0 + row) * kDM + k0 + kk);
            As[kk + 0][row] = v.x; As[kk + 1][row] = v.y;
            As[kk + 2][row] = v.z; As[kk + 3][row] = v.w;
        }
        {
            int n  = tid >> 2;
            int kk = (tid & 3) * 4;
            float4 v = *reinterpret_cast<const float4*>(W + (c0 + n) * kDM + k0 + kk);
            Bs[kk + 0][n] = v.x; Bs[kk + 1][n] = v.y;
            Bs[kk + 2][n] = v.z; Bs[kk + 3][n] = v.w;
        }
        __syncthreads();

        #pragma unroll
        for (int k = 0; k < PBK; ++k) {
            float4 a0 = *reinterpret_cast<const float4*>(&As[k][ty * 8]);
            float4 a1 = *reinterpret_cast<const float4*>(&As[k][ty * 8 + 4]);
            float4 bb = *reinterpret_cast<const float4*>(&Bs[k][tx * 4]);
            float a[8] = {a0.x, a0.y, a0.z, a0.w, a1.x, a1.y, a1.z, a1.w};
            float b[4] = {bb.x, bb.y, bb.z, bb.w};
            #pragma unroll
            for (int i = 0; i < 8; ++i)
                #pragma unroll
                for (int j = 0; j < 4; ++j)
                    acc[i][j] = fmaf(a[i], b[j], acc[i][j]);
        }
        __syncthreads();
    }

    #pragma unroll
    for (int i = 0; i < 8; ++i) {
        const int row = n0 + ty * 8 + i;
        const int bb  = row / kS;
        const int ss  = row % kS;
        #pragma unroll
        for (int j = 0; j < 4; ++j) {
            const int col = c0 + tx * 4 + j;
            const int h = col >> 5, d = col & 31;
            const int r = (bb * kH + h) * kS + ss;
            float val = acc[i][j] + bias[col];
            if (z == 2) {
                g_v[r * kDK + d] = val;
            } else {
                if (z == 0) val *= kScale;           // pre-scale Q
                __nv_bfloat16 hi = __float2bfloat16(val);
                __nv_bfloat16 lo = __float2bfloat16(val - __bfloat162float(hi));
                __nv_bfloat16* dst = (z == 0) ? g_qcat : g_kcat;
                dst[r * kKC + d]       = hi;
                dst[r * kKC + 32 + d]  = lo;
            }
        }
    }
}

// ---------------------------------------------------------------------------
// Kernel 2 — score GEMM on mma.sync bf16 (hi/lo split, fp32 accumulate):
// S = Qs_hi.Khi + Qs_lo.Khi + Qs_hi.Klo  (lo.lo dropped, <=2^-16 rel).
// CTA tile 128(i) x 64(j); 8 warps as 4(m) x 2(n); warp tile 32x32.
// Small tile -> 32 acc regs -> 3 CTAs/SM (vs 2) for latency hiding.
// Epilogue stores dense scores + exact per-tile row maxes.
// ---------------------------------------------------------------------------
__global__ __launch_bounds__(256, 3)
void score_gemm_tc(void)
{
    __shared__ __align__(128) char sA[128 * 128];   // Qcat tile, SW128 (16 KB)
    __shared__ __align__(128) char sB[kJT * 128];   // Kcat tile, SW128 (8 KB)
    __shared__ float sTmax[128][2];

    const int bh = blockIdx.z;
    const int i0 = blockIdx.y * 128;
    const int j0 = blockIdx.x * kJT;
    const int tid  = threadIdx.x;
    const int wid  = tid >> 5;
    const int lane = tid & 31;

    const uint32_t sAu = smem_u32(sA);
    const uint32_t sBu = smem_u32(sB);

    // Stage A (128 rows) and B (64 rows), 128 B/row, SW128-swizzled
    {
        const uint4* __restrict__ Ag = reinterpret_cast<const uint4*>(
            g_qcat + ((size_t)bh * kS + i0) * kKC);
        const uint4* __restrict__ Bg = reinterpret_cast<const uint4*>(
            g_kcat + ((size_t)bh * kS + j0) * kKC);
        #pragma unroll
        for (int r = 0; r < 4; ++r) {
            const int f   = tid + r * 256;
            const int row = f >> 3;
            const int c16 = f & 7;
            const uint32_t off = SW128((uint32_t)(row * 128 + c16 * 16));
            *reinterpret_cast<uint4*>(sA + off) = Ag[row * 8 + c16];
        }
        #pragma unroll
        for (int r = 0; r < 2; ++r) {
            const int f   = tid + r * 256;
            const int row = f >> 3;
            const int c16 = f & 7;
            const uint32_t off = SW128((uint32_t)(row * 128 + c16 * 16));
            *reinterpret_cast<uint4*>(sB + off) = Bg[row * 8 + c16];
        }
    }
    __syncthreads();

    const int wm = wid & 3;            // 4 warps cover 128 rows
    const int wn = wid >> 2;           // 2 warps cover 64 cols
    const int imb = wm * 32;
    const int jnb = wn * 32;

    float acc[2][4][4];
    #pragma unroll
    for (int mt = 0; mt < 2; ++mt)
        #pragma unroll
        for (int nt = 0; nt < 4; ++nt)
            #pragma unroll
            for (int e = 0; e < 4; ++e) acc[mt][nt][e] = 0.0f;

    // 3 product passes x 2 k16-steps
    const int aoff[3] = {0, 32, 0};
    const int boff[3] = {0, 0, 32};
    #pragma unroll
    for (int p = 0; p < 3; ++p) {
        #pragma unroll
        for (int kk = 0; kk < 32; kk += 16) {
            const int kcA = aoff[p] + kk;
            const int kcB = boff[p] + kk;

            uint32_t af[2][4];
            #pragma unroll
            for (int mt = 0; mt < 2; ++mt) {
                const int row = imb + mt * 16 + (lane & 15);
                const int chk = (kcA >> 3) + (lane >> 4);
                ldsm_x4(af[mt], sAu + SW128((uint32_t)(row * 128 + chk * 16)));
            }
            uint32_t bf[4][2];
            #pragma unroll
            for (int np = 0; np < 2; ++np) {
                const int row = jnb + np * 16 + (lane & 7) + ((lane & 16) >> 1);
                const int chk = (kcB >> 3) + ((lane >> 3) & 1);
                uint32_t r4[4];
                ldsm_x4(r4, sBu + SW128((uint32_t)(row * 128 + chk * 16)));
                bf[np * 2 + 0][0] = r4[0]; bf[np * 2 + 0][1] = r4[1];
                bf[np * 2 + 1][0] = r4[2]; bf[np * 2 + 1][1] = r4[3];
            }
            #pragma unroll
            for (int mt = 0; mt < 2; ++mt)
                #pragma unroll
                for (int nt = 0; nt < 4; ++nt)
                    mma_bf16(acc[mt][nt], af[mt], bf[nt]);
        }
    }

    // Epilogue: store scores (float2) + exact per-tile row maxes.
    const int g  = lane >> 2;
    const int tg = lane & 3;
    float2* __restrict__ Sbase = reinterpret_cast<float2*>(
        g_s + ((size_t)bh * kS + i0) * kS + j0);

    #pragma unroll
    for (int mt = 0; mt < 2; ++mt) {
        const int r0 = imb + mt * 16 + g;
        float rm0 = -FLT_MAX, rm1 = -FLT_MAX;
        #pragma unroll
        for (int nt = 0; nt < 4; ++nt) {
            const int c2 = (jnb + nt * 8 + tg * 2) >> 1;
            float2 lo = make_float2(acc[mt][nt][0], acc[mt][nt][1]);
            float2 hi = make_float2(acc[mt][nt][2], acc[mt][nt][3]);
            Sbase[(size_t)r0 * (kS / 2) + c2]       = lo;
            Sbase[(size_t)(r0 + 8) * (kS / 2) + c2] = hi;
            rm0 = fmaxf(rm0, fmaxf(lo.x, lo.y));
            rm1 = fmaxf(rm1, fmaxf(hi.x, hi.y));
        }
        rm0 = fmaxf(rm0, __shfl_xor_sync(0xffffffffu, rm0, 1));
        rm0 = fmaxf(rm0, __shfl_xor_sync(0xffffffffu, rm0, 2));
        rm1 = fmaxf(rm1, __shfl_xor_sync(0xffffffffu, rm1, 1));
        rm1 = fmaxf(rm1, __shfl_xor_sync(0xffffffffu, rm1, 2));
        if (tg == 0) {
            sTmax[r0][wn]     = rm0;
            sTmax[r0 + 8][wn] = rm1;
        }
    }
    __syncthreads();
    if (tid < 128) {
        g_tilemax[((size_t)bh * kS + i0 + tid) * kNT + blockIdx.x] =
            fmaxf(sTmax[tid][0], sTmax[tid][1]);
    }
}

// ---------------------------------------------------------------------------
// Exact slow fallback for a row whose candidate list overflowed (rare):
// reads the DENSE stored scores (cheap), Michelot + ballot-pop AV.
// ---------------------------------------------------------------------------
__device__ __noinline__ float slow_row(const float4* __restrict__ S4,
                                       const float* __restrict__ Vbh,
                                       float thr, int lane)
{
    float tau = thr;
    int prev = -1;
    for (int it = 0; it < 200; ++it) {
        float sum = 0.0f; int cnt = 0;
        for (int c = lane; c < kS / 4; c += 32) {
            float4 v = __ldg(S4 + c);
            if (v.x > tau) { sum += v.x; ++cnt; }
            if (v.y > tau) { sum += v.y; ++cnt; }
            if (v.z > tau) { sum += v.z; ++cnt; }
            if (v.w > tau) { sum += v.w; ++cnt; }
        }
        #pragma unroll
        for (int o = 16; o; o >>= 1) {
            sum += __shfl_xor_sync(0xffffffffu, sum, o);
            cnt += __shfl_xor_sync(0xffffffffu, cnt, o);
        }
        if (cnt == prev || cnt == 0) break;
        tau = (sum - 1.0f) / (float)cnt;
        prev = cnt;
    }
    float a = 0.0f;
    for (int c = lane; c < kS / 4; c += 32) {
        float4 v = __ldg(S4 + c);
        const float vv[4] = {v.x, v.y, v.z, v.w};
        #pragma unroll
        for (int e = 0; e < 4; ++e) {
            float w = vv[e] - tau;
            unsigned mk = __ballot_sync(0xffffffffu, w > 0.0f);
            while (mk) {
                int b = __ffs(mk) - 1;
                mk &= mk - 1;
                float wb = __shfl_sync(0xffffffffu, w, b);
                int jj = __shfl_sync(0xffffffffu, c * 4 + e, b);
                a = fmaf(wb, __ldg(Vbh + jj * kDK + lane), a);
            }
        }
    }
    return a;
}

// ---------------------------------------------------------------------------
// Kernel 3 — sparsemax + AV, tile-selective (64-col tiles now). 1 warp/row.
// Reads 32 tilemaxes -> exact row max -> scans only tiles with tmax > m-1.
// ---------------------------------------------------------------------------
__global__ __launch_bounds__(256, 2)
void sparsemax_av(float* __restrict__ out)
{
    __shared__ float2 Lists[8][kCap];

    const int bh   = blockIdx.y;
    const int warp = threadIdx.x >> 5;
    const int lane = threadIdx.x & 31;
    const unsigned lmask = (1u << lane) - 1u;
    const int qi   = blockIdx.x * 8 + warp;

    const float4* __restrict__ S4 =
        reinterpret_cast<const float4*>(g_s + ((size_t)bh * kS + qi) * kS);
    const float* __restrict__ Vbh = g_v + bh * kS * kDK;

    // Row max from the 32 tile maxes (exact)
    float tm = __ldg(g_tilemax + ((size_t)bh * kS + qi) * kNT + lane);
    float m = tm;
    #pragma unroll
    for (int o = 16; o; o >>= 1)
        m = fmaxf(m, __shfl_xor_sync(0xffffffffu, m, o));
    const float thr = m - 1.0f;
    unsigned tmask = __ballot_sync(0xffffffffu, tm > thr);

    // Candidate compaction over selected 64-col tiles only
    float2* __restrict__ Lq = Lists[warp];
    int n = 0;
    unsigned it = tmask;
    while (it && n <= kCap) {
        const int t = __ffs(it) - 1;
        it &= it - 1;
        float4 v = (lane < 16) ? __ldg(S4 + t * 16 + lane)
                               : make_float4(-FLT_MAX, -FLT_MAX, -FLT_MAX, -FLT_MAX);
        const int jb = t * kJT + lane * 4;
        const float vv[4] = {v.x, v.y, v.z, v.w};
        #pragma unroll
        for (int e = 0; e < 4; ++e) {
            const bool cand = vv[e] > thr;
            const unsigned mk = __ballot_sync(0xffffffffu, cand);
            if (mk) {
                const int idx = n + __popc(mk & lmask);
                if (cand && idx < kCap)
                    Lq[idx] = make_float2(vv[e], __int_as_float(jb + e));
                n += __popc(mk);
            }
        }
    }
    __syncwarp();

    float a;
    if (n <= kCap) {
        float c0 = (lane      < n) ? Lq[lane     ].x : -FLT_MAX;
        float c1 = (lane + 32 < n) ? Lq[lane + 32].x : -FLT_MAX;
        float c2 = (lane + 64 < n) ? Lq[lane + 64].x : -FLT_MAX;
        float c3 = (lane + 96 < n) ? Lq[lane + 96].x : -FLT_MAX;
        float tau = thr;
        int prev = -1;
        for (int iter = 0; iter < 80; ++iter) {
            float sum = 0.0f; int cnt = 0;
            if (c0 > tau) { sum += c0; ++cnt; }
            if (c1 > tau) { sum += c1; ++cnt; }
            if (c2 > tau) { sum += c2; ++cnt; }
            if (c3 > tau) { sum += c3; ++cnt; }
            #pragma unroll
            for (int o = 16; o; o >>= 1) {
                sum += __shfl_xor_sync(0xffffffffu, sum, o);
                cnt += __shfl_xor_sync(0xffffffffu, cnt, o);
            }
            if (cnt == prev || cnt == 0) break;
            tau = (sum - 1.0f) / (float)cnt;
            prev = cnt;
        }
        float a0 = 0.0f, a1 = 0.0f;
        int ci = 0;
        for (; ci + 2 <= n; ci += 2) {
            float2 p0 = Lq[ci], p1 = Lq[ci + 1];
            float w0 = fmaxf(p0.x - tau, 0.0f);
            float w1 = fmaxf(p1.x - tau, 0.0f);
            a0 = fmaf(w0, __ldg(Vbh + __float_as_int(p0.y) * kDK + lane), a0);
            a1 = fmaf(w1, __ldg(Vbh + __float_as_int(p1.y) * kDK + lane), a1);
        }
        if (ci < n) {
            float2 p = Lq[ci];
            float w = fmaxf(p.x - tau, 0.0f);
            a0 = fmaf(w, __ldg(Vbh + __float_as_int(p.y) * kDK + lane), a0);
        }
        a = a0 + a1;
    } else {
        a = slow_row(S4, Vbh, thr, lane);
    }

    const int bb = bh >> 3;
    const int h  = bh & 7;
    out[(bb * kS + qi) * kDM + h * kDK + lane] = a;
}

// ---------------------------------------------------------------------------
extern "C" void kernel_launch(void* const* d_in, const int* in_sizes, int n_in,
                              void* d_out, int out_size)
{
    const float* query = (const float*)d_in[0];
    const float* key   = (const float*)d_in[1];
    const float* value = (const float*)d_in[2];
    const float* Wq    = (const float*)d_in[3];
    const float* bq    = (const float*)d_in[4];
    const float* Wk    = (const float*)d_in[5];
    const float* bk    = (const float*)d_in[6];
    const float* Wv    = (const float*)d_in[7];
    const float* bv    = (const float*)d_in[8];
    float* out = (float*)d_out;

    dim3 pgrid(kDM / 64, kNRow / 128, 3);      // (4, 32, 3)
    proj_kernel<<<pgrid, 256>>>(query, key, value, Wq, bq, Wk, bk, Wv, bv);

    dim3 sgrid(kS / kJT, kS / 128, kB * kH);   // (32, 16, 16)
    score_gemm_tc<<<sgrid, 256>>>();

    dim3 agrid(kS / 8, kB * kH);               // (256, 16)
    sparsemax_av<<<agrid, 256>>>(out);

    (void)in_sizes; (void)n_in; (void)out_size;
}

// round 14
// speedup vs baseline: 8.3488x; 1.1469x over previous
#include <cuda_runtime.h>
#include <cuda_bf16.h>
#include <cfloat>
#include <cstdint>

namespace {
constexpr int kB  = 2;
constexpr int kH  = 8;
constexpr int kS  = 2048;
constexpr int kDK = 32;
constexpr int kDM = 256;
constexpr int kNRow = kB * kS;           // 4096
constexpr float kScale = 0.17677669529663687f;  // 1/sqrt(32)
constexpr int kCap = 128;                // candidate cap per query row
constexpr int kKC  = 64;                 // cat K: [hi(32) | lo(32)] bf16
constexpr int kNT  = kS / 128;           // 16 column tiles per row
}

// Scratch buffers.
__device__ float g_v[kB * kH * kS * kDK];                 // V fp32
__device__ __nv_bfloat16 g_qcat[kB * kH * kS * kKC];      // [Qhi*scale | Qlo*scale]
__device__ __nv_bfloat16 g_kcat[kB * kH * kS * kKC];      // [Khi | Klo]
__device__ float g_s[(size_t)kB * kH * kS * kS];          // scores (256 MiB)
__device__ float g_tilemax[(size_t)kB * kH * kS * kNT];   // per-row per-tile max (exact)

// ---------------------------------------------------------------------------
// Helpers
// ---------------------------------------------------------------------------
__device__ __forceinline__ uint32_t smem_u32(const void* p) {
    uint32_t a;
    asm("{ .reg .u64 t; cvta.to.shared.u64 t, %1; cvt.u32.u64 %0, t; }"
        : "=r"(a) : "l"(p));
    return a;
}
__device__ __forceinline__ void ldsm_x4(uint32_t* r, uint32_t addr) {
    asm volatile("ldmatrix.sync.aligned.m8n8.x4.shared.b16 {%0,%1,%2,%3}, [%4];"
                 : "=r"(r[0]), "=r"(r[1]), "=r"(r[2]), "=r"(r[3]) : "r"(addr));
}
__device__ __forceinline__ void mma_bf16(float* d, const uint32_t* a, const uint32_t* b) {
    asm volatile(
        "mma.sync.aligned.m16n8k16.row.col.f32.bf16.bf16.f32 "
        "{%0,%1,%2,%3}, {%4,%5,%6,%7}, {%8,%9}, {%0,%1,%2,%3};"
        : "+f"(d[0]), "+f"(d[1]), "+f"(d[2]), "+f"(d[3])
        : "r"(a[0]), "r"(a[1]), "r"(a[2]), "r"(a[3]), "r"(b[0]), "r"(b[1]));
}
#define SW128(off) ((off) ^ (((off) >> 3) & 0x70))

// ---------------------------------------------------------------------------
// Kernel 1 — projection GEMM; epilogue emits V fp32 and bf16 hi/lo cat
// buffers (Q pre-scaled by 1/sqrt(dk)).
// ---------------------------------------------------------------------------
__global__ __launch_bounds__(256)
void proj_kernel(const float* __restrict__ xq, const float* __restrict__ xk,
                 const float* __restrict__ xv,
                 const float* __restrict__ wq, const float* __restrict__ bq,
                 const float* __restrict__ wk, const float* __restrict__ bk,
                 const float* __restrict__ wv, const float* __restrict__ bv)
{
    constexpr int PBM = 128, PBN = 64, PBK = 16;
    __shared__ float As[PBK][PBM];
    __shared__ float Bs[PBK][PBN];

    const int z = blockIdx.z;
    const float* __restrict__ X    = (z == 0) ? xq : (z == 1) ? xk : xv;
    const float* __restrict__ W    = (z == 0) ? wq : (z == 1) ? wk : wv;
    const float* __restrict__ bias = (z == 0) ? bq : (z == 1) ? bk : bv;

    const int n0 = blockIdx.y * PBM;
    const int c0 = blockIdx.x * PBN;
    const int tid = threadIdx.x;
    const int tx = tid & 15;
    const int ty = tid >> 4;

    float acc[8][4];
    #pragma unroll
    for (int i = 0; i < 8; ++i)
        #pragma unroll
        for (int j = 0; j < 4; ++j) acc[i][j] = 0.0f;

    for (int k0 = 0; k0 < kDM; k0 += PBK) {
        #pragma unroll
        for (int r = 0; r < 2; ++r) {
            int f   = tid + r * 256;
            int row = f >> 2;
            int kk  = (f & 3) * 4;
            float4 v = *reinterpret_cast<const float4*>(X + (n0 + row) * kDM + k0 + kk);
            As[kk + 0][row] = v.x; As[kk + 1][row] = v.y;
            As[kk + 2][row] = v.z; As[kk + 3][row] = v.w;
        }
        {
            int n  = tid >> 2;
            int kk = (tid & 3) * 4;
            float4 v = *reinterpret_cast<const float4*>(W + (c0 + n) * kDM + k0 + kk);
            Bs[kk + 0][n] = v.x; Bs[kk + 1][n] = v.y;
            Bs[kk + 2][n] = v.z; Bs[kk + 3][n] = v.w;
        }
        __syncthreads();

        #pragma unroll
        for (int k = 0; k < PBK; ++k) {
            float4 a0 = *reinterpret_cast<const float4*>(&As[k][ty * 8]);
            float4 a1 = *reinterpret_cast<const float4*>(&As[k][ty * 8 + 4]);
            float4 bb = *reinterpret_cast<const float4*>(&Bs[k][tx * 4]);
            float a[8] = {a0.x, a0.y, a0.z, a0.w, a1.x, a1.y, a1.z, a1.w};
            float b[4] = {bb.x, bb.y, bb.z, bb.w};
            #pragma unroll
            for (int i = 0; i < 8; ++i)
                #pragma unroll
                for (int j = 0; j < 4; ++j)
                    acc[i][j] = fmaf(a[i], b[j], acc[i][j]);
        }
        __syncthreads();
    }

    #pragma unroll
    for (int i = 0; i < 8; ++i) {
        const int row = n0 + ty * 8 + i;
        const int bb  = row / kS;
        const int ss  = row % kS;
        #pragma unroll
        for (int j = 0; j < 4; ++j) {
            const int col = c0 + tx * 4 + j;
            const int h = col >> 5, d = col & 31;
            const int r = (bb * kH + h) * kS + ss;
            float val = acc[i][j] + bias[col];
            if (z == 2) {
                g_v[r * kDK + d] = val;
            } else {
                if (z == 0) val *= kScale;           // pre-scale Q
                __nv_bfloat16 hi = __float2bfloat16(val);
                __nv_bfloat16 lo = __float2bfloat16(val - __bfloat162float(hi));
                __nv_bfloat16* dst = (z == 0) ? g_qcat : g_kcat;
                dst[r * kKC + d]       = hi;
                dst[r * kKC + 32 + d]  = lo;
            }
        }
    }
}

// ---------------------------------------------------------------------------
// Kernel 2 — score GEMM on mma.sync bf16 (hi/lo split, fp32 accumulate):
// S = Qhi.Khi + Qlo.Khi + Qhi.Klo  (lo.lo dropped, <=2^-16 rel).
// CTA 128x128 tile; 8 warps as 4(m) x 2(n); warp tile 32x64.
// Fragment-reuse order: per k16-step load A(hi,lo) once and per nt-half
// B(hi,lo) once, then issue all 3 products from registers (36->24 LDSM).
// Epilogue stores dense scores + exact per-tile row maxes.
// ---------------------------------------------------------------------------
__global__ __launch_bounds__(256, 2)
void score_gemm_tc(void)
{
    __shared__ __align__(128) char sA[128 * 128];   // Qcat tile, SW128
    __shared__ __align__(128) char sB[128 * 128];   // Kcat tile, SW128
    __shared__ float sTmax[128][2];

    const int bh = blockIdx.z;
    const int i0 = blockIdx.y * 128;
    const int j0 = blockIdx.x * 128;
    const int tid  = threadIdx.x;
    const int wid  = tid >> 5;
    const int lane = tid & 31;

    const uint32_t sAu = smem_u32(sA);
    const uint32_t sBu = smem_u32(sB);

    // Stage A, B tiles (128 rows x 128 B each), SW128-swizzled
    {
        const uint4* __restrict__ Ag = reinterpret_cast<const uint4*>(
            g_qcat + ((size_t)bh * kS + i0) * kKC);
        const uint4* __restrict__ Bg = reinterpret_cast<const uint4*>(
            g_kcat + ((size_t)bh * kS + j0) * kKC);
        #pragma unroll
        for (int r = 0; r < 4; ++r) {
            const int f   = tid + r * 256;
            const int row = f >> 3;
            const int c16 = f & 7;
            const uint32_t off = SW128((uint32_t)(row * 128 + c16 * 16));
            *reinterpret_cast<uint4*>(sA + off) = Ag[row * 8 + c16];
            *reinterpret_cast<uint4*>(sB + off) = Bg[row * 8 + c16];
        }
    }
    __syncthreads();

    const int wm = wid & 3;            // 4 warps cover 128 rows
    const int wn = wid >> 2;           // 2 warps cover 128 cols
    const int imb = wm * 32;
    const int jnb = wn * 64;

    float acc[2][8][4];
    #pragma unroll
    for (int mt = 0; mt < 2; ++mt)
        #pragma unroll
        for (int nt = 0; nt < 8; ++nt)
            #pragma unroll
            for (int e = 0; e < 4; ++e) acc[mt][nt][e] = 0.0f;

    // Fragment-reuse mainloop: kk in {0,16}; A hi at kk, A lo at kk+32.
    #pragma unroll
    for (int kk = 0; kk < 32; kk += 16) {
        uint32_t afh[2][4], afl[2][4];
        #pragma unroll
        for (int mt = 0; mt < 2; ++mt) {
            const int row = imb + mt * 16 + (lane & 15);
            const int chkh = (kk >> 3) + (lane >> 4);
            const int chkl = ((kk + 32) >> 3) + (lane >> 4);
            ldsm_x4(afh[mt], sAu + SW128((uint32_t)(row * 128 + chkh * 16)));
            ldsm_x4(afl[mt], sAu + SW128((uint32_t)(row * 128 + chkl * 16)));
        }
        #pragma unroll
        for (int half = 0; half < 2; ++half) {
            uint32_t bfh[4][2], bfl[4][2];
            #pragma unroll
            for (int np = 0; np < 2; ++np) {
                const int row = jnb + half * 32 + np * 16
                              + (lane & 7) + ((lane & 16) >> 1);
                const int chkh = (kk >> 3) + ((lane >> 3) & 1);
                const int chkl = ((kk + 32) >> 3) + ((lane >> 3) & 1);
                uint32_t r4[4];
                ldsm_x4(r4, sBu + SW128((uint32_t)(row * 128 + chkh * 16)));
                bfh[np * 2 + 0][0] = r4[0]; bfh[np * 2 + 0][1] = r4[1];
                bfh[np * 2 + 1][0] = r4[2]; bfh[np * 2 + 1][1] = r4[3];
                ldsm_x4(r4, sBu + SW128((uint32_t)(row * 128 + chkl * 16)));
                bfl[np * 2 + 0][0] = r4[0]; bfl[np * 2 + 0][1] = r4[1];
                bfl[np * 2 + 1][0] = r4[2]; bfl[np * 2 + 1][1] = r4[3];
            }
            #pragma unroll
            for (int mt = 0; mt < 2; ++mt)
                #pragma unroll
                for (int nt4 = 0; nt4 < 4; ++nt4) {
                    float* a = acc[mt][half * 4 + nt4];
                    mma_bf16(a, afh[mt], bfh[nt4]);   // hi.hi
                    mma_bf16(a, afl[mt], bfh[nt4]);   // lo.hi
                    mma_bf16(a, afh[mt], bfl[nt4]);   // hi.lo
                }
        }
    }

    // Epilogue: store scores (float2) + exact per-tile row maxes.
    const int g  = lane >> 2;
    const int tg = lane & 3;
    float2* __restrict__ Sbase = reinterpret_cast<float2*>(
        g_s + ((size_t)bh * kS + i0) * kS + j0);

    #pragma unroll
    for (int mt = 0; mt < 2; ++mt) {
        const int r0 = imb + mt * 16 + g;
        float rm0 = -FLT_MAX, rm1 = -FLT_MAX;
        #pragma unroll
        for (int nt = 0; nt < 8; ++nt) {
            const int c2 = (jnb + nt * 8 + tg * 2) >> 1;
            float2 lo = make_float2(acc[mt][nt][0], acc[mt][nt][1]);
            float2 hi = make_float2(acc[mt][nt][2], acc[mt][nt][3]);
            Sbase[(size_t)r0 * (kS / 2) + c2]       = lo;
            Sbase[(size_t)(r0 + 8) * (kS / 2) + c2] = hi;
            rm0 = fmaxf(rm0, fmaxf(lo.x, lo.y));
            rm1 = fmaxf(rm1, fmaxf(hi.x, hi.y));
        }
        rm0 = fmaxf(rm0, __shfl_xor_sync(0xffffffffu, rm0, 1));
        rm0 = fmaxf(rm0, __shfl_xor_sync(0xffffffffu, rm0, 2));
        rm1 = fmaxf(rm1, __shfl_xor_sync(0xffffffffu, rm1, 1));
        rm1 = fmaxf(rm1, __shfl_xor_sync(0xffffffffu, rm1, 2));
        if (tg == 0) {
            sTmax[r0][wn]     = rm0;
            sTmax[r0 + 8][wn] = rm1;
        }
    }
    __syncthreads();
    if (tid < 128) {
        g_tilemax[((size_t)bh * kS + i0 + tid) * kNT + blockIdx.x] =
            fmaxf(sTmax[tid][0], sTmax[tid][1]);
    }
}

// ---------------------------------------------------------------------------
// Exact slow fallback for a row whose candidate list overflowed (rare):
// reads the DENSE stored scores (cheap), Michelot + ballot-pop AV.
// ---------------------------------------------------------------------------
__device__ __noinline__ float slow_row(const float4* __restrict__ S4,
                                       const float* __restrict__ Vbh,
                                       float thr, int lane)
{
    float tau = thr;
    int prev = -1;
    for (int it = 0; it < 200; ++it) {
        float sum = 0.0f; int cnt = 0;
        for (int c = lane; c < kS / 4; c += 32) {
            float4 v = __ldg(S4 + c);
            if (v.x > tau) { sum += v.x; ++cnt; }
            if (v.y > tau) { sum += v.y; ++cnt; }
            if (v.z > tau) { sum += v.z; ++cnt; }
            if (v.w > tau) { sum += v.w; ++cnt; }
        }
        #pragma unroll
        for (int o = 16; o; o >>= 1) {
            sum += __shfl_xor_sync(0xffffffffu, sum, o);
            cnt += __shfl_xor_sync(0xffffffffu, cnt, o);
        }
        if (cnt == prev || cnt == 0) break;
        tau = (sum - 1.0f) / (float)cnt;
        prev = cnt;
    }
    float a = 0.0f;
    for (int c = lane; c < kS / 4; c += 32) {
        float4 v = __ldg(S4 + c);
        const float vv[4] = {v.x, v.y, v.z, v.w};
        #pragma unroll
        for (int e = 0; e < 4; ++e) {
            float w = vv[e] - tau;
            unsigned mk = __ballot_sync(0xffffffffu, w > 0.0f);
            while (mk) {
                int b = __ffs(mk) - 1;
                mk &= mk - 1;
                float wb = __shfl_sync(0xffffffffu, w, b);
                int jj = __shfl_sync(0xffffffffu, c * 4 + e, b);
                a = fmaf(wb, __ldg(Vbh + jj * kDK + lane), a);
            }
        }
    }
    return a;
}

// ---------------------------------------------------------------------------
// Kernel 3 — sparsemax + AV, tile-selective. 1 warp per query row.
// Reads 16 tilemaxes -> exact row max -> scans only tiles with tmax > m-1.
// ---------------------------------------------------------------------------
__global__ __launch_bounds__(256, 2)
void sparsemax_av(float* __restrict__ out)
{
    __shared__ float2 Lists[8][kCap];

    const int bh   = blockIdx.y;
    const int warp = threadIdx.x >> 5;
    const int lane = threadIdx.x & 31;
    const unsigned lmask = (1u << lane) - 1u;
    const int qi   = blockIdx.x * 8 + warp;

    const float4* __restrict__ S4 =
        reinterpret_cast<const float4*>(g_s + ((size_t)bh * kS + qi) * kS);
    const float* __restrict__ Vbh = g_v + bh * kS * kDK;

    // Row max from the 16 tile maxes (exact)
    float tm = (lane < kNT)
        ? __ldg(g_tilemax + ((size_t)bh * kS + qi) * kNT + lane) : -FLT_MAX;
    float m = tm;
    #pragma unroll
    for (int o = 16; o; o >>= 1)
        m = fmaxf(m, __shfl_xor_sync(0xffffffffu, m, o));
    const float thr = m - 1.0f;
    unsigned tmask = __ballot_sync(0xffffffffu, lane < kNT && tm > thr);

    // Candidate compaction over selected 128-col tiles only
    float2* __restrict__ Lq = Lists[warp];
    int n = 0;
    unsigned it = tmask;
    while (it && n <= kCap) {
        const int t = __ffs(it) - 1;
        it &= it - 1;
        float4 v = __ldg(S4 + t * 32 + lane);
        const int jb = t * 128 + lane * 4;
        const float vv[4] = {v.x, v.y, v.z, v.w};
        #pragma unroll
        for (int e = 0; e < 4; ++e) {
            const bool cand = vv[e] > thr;
            const unsigned mk = __ballot_sync(0xffffffffu, cand);
            if (mk) {
                const int idx = n + __popc(mk & lmask);
                if (cand && idx < kCap)
                    Lq[idx] = make_float2(vv[e], __int_as_float(jb + e));
                n += __popc(mk);
            }
        }
    }
    __syncwarp();

    float a;
    if (n <= kCap) {
        float c0 = (lane      < n) ? Lq[lane     ].x : -FLT_MAX;
        float c1 = (lane + 32 < n) ? Lq[lane + 32].x : -FLT_MAX;
        float c2 = (lane + 64 < n) ? Lq[lane + 64].x : -FLT_MAX;
        float c3 = (lane + 96 < n) ? Lq[lane + 96].x : -FLT_MAX;
        float tau = thr;
        int prev = -1;
        for (int iter = 0; iter < 80; ++iter) {
            float sum = 0.0f; int cnt = 0;
            if (c0 > tau) { sum += c0; ++cnt; }
            if (c1 > tau) { sum += c1; ++cnt; }
            if (c2 > tau) { sum += c2; ++cnt; }
            if (c3 > tau) { sum += c3; ++cnt; }
            #pragma unroll
            for (int o = 16; o; o >>= 1) {
                sum += __shfl_xor_sync(0xffffffffu, sum, o);
                cnt += __shfl_xor_sync(0xffffffffu, cnt, o);
            }
            if (cnt == prev || cnt == 0) break;
            tau = (sum - 1.0f) / (float)cnt;
            prev = cnt;
        }
        float a0 = 0.0f, a1 = 0.0f;
        int ci = 0;
        for (; ci + 2 <= n; ci += 2) {
            float2 p0 = Lq[ci], p1 = Lq[ci + 1];
            float w0 = fmaxf(p0.x - tau, 0.0f);
            float w1 = fmaxf(p1.x - tau, 0.0f);
            a0 = fmaf(w0, __ldg(Vbh + __float_as_int(p0.y) * kDK + lane), a0);
            a1 = fmaf(w1, __ldg(Vbh + __float_as_int(p1.y) * kDK + lane), a1);
        }
        if (ci < n) {
            float2 p = Lq[ci];
            float w = fmaxf(p.x - tau, 0.0f);
            a0 = fmaf(w, __ldg(Vbh + __float_as_int(p.y) * kDK + lane), a0);
        }
        a = a0 + a1;
    } else {
        a = slow_row(S4, Vbh, thr, lane);
    }

    const int bb = bh >> 3;
    const int h  = bh & 7;
    out[(bb * kS + qi) * kDM + h * kDK + lane] = a;
}

// ---------------------------------------------------------------------------
extern "C" void kernel_launch(void* const* d_in, const int* in_sizes, int n_in,
                              void* d_out, int out_size)
{
    const float* query = (const float*)d_in[0];
    const float* key   = (const float*)d_in[1];
    const float* value = (const float*)d_in[2];
    const float* Wq    = (const float*)d_in[3];
    const float* bq    = (const float*)d_in[4];
    const float* Wk    = (const float*)d_in[5];
    const float* bk    = (const float*)d_in[6];
    const float* Wv    = (const float*)d_in[7];
    const float* bv    = (const float*)d_in[8];
    float* out = (float*)d_out;

    dim3 pgrid(kDM / 64, kNRow / 128, 3);      // (4, 32, 3)
    proj_kernel<<<pgrid, 256>>>(query, key, value, Wq, bq, Wk, bk, Wv, bv);

    dim3 sgrid(kS / 128, kS / 128, kB * kH);   // (16, 16, 16)
    score_gemm_tc<<<sgrid, 256>>>();

    dim3 agrid(kS / 8, kB * kH);               // (256, 16)
    sparsemax_av<<<agrid, 256>>>(out);

    (void)in_sizes; (void)n_in; (void)out_size;
}

// round 15
// speedup vs baseline: 8.6843x; 1.0402x over previous
#include <cuda_runtime.h>
#include <cuda_bf16.h>
#include <cfloat>
#include <cstdint>

namespace {
constexpr int kB  = 2;
constexpr int kH  = 8;
constexpr int kS  = 2048;
constexpr int kDK = 32;
constexpr int kDM = 256;
constexpr int kNRow = kB * kS;           // 4096
constexpr float kScale = 0.17677669529663687f;  // 1/sqrt(32)
constexpr int kCap = 128;                // candidate cap per query row
constexpr int kKC  = 64;                 // cat K: [hi(32) | lo(32)] bf16
constexpr int kNT  = kS / 128;           // 16 column tiles per row
constexpr int kJL  = 4;                  // j-tiles per score CTA
constexpr int kTileB = 128 * 128;        // 16 KB tile
constexpr int kSmemScore = kTileB * 3;   // A + 2x B buffers = 48 KB
}

// Scratch buffers.
__device__ float g_v[kB * kH * kS * kDK];                 // V fp32
__device__ __nv_bfloat16 g_qcat[kB * kH * kS * kKC];      // [Qhi*scale | Qlo*scale]
__device__ __nv_bfloat16 g_kcat[kB * kH * kS * kKC];      // [Khi | Klo]
__device__ float g_s[(size_t)kB * kH * kS * kS];          // scores (256 MiB)
__device__ float g_tmax2[(size_t)kB * kH * kS * kNT * 2]; // per-row per-tile max, 2 slots

// ---------------------------------------------------------------------------
// Helpers
// ---------------------------------------------------------------------------
__device__ __forceinline__ uint32_t smem_u32(const void* p) {
    uint32_t a;
    asm("{ .reg .u64 t; cvta.to.shared.u64 t, %1; cvt.u32.u64 %0, t; }"
        : "=r"(a) : "l"(p));
    return a;
}
__device__ __forceinline__ void ldsm_x4(uint32_t* r, uint32_t addr) {
    asm volatile("ldmatrix.sync.aligned.m8n8.x4.shared.b16 {%0,%1,%2,%3}, [%4];"
                 : "=r"(r[0]), "=r"(r[1]), "=r"(r[2]), "=r"(r[3]) : "r"(addr));
}
__device__ __forceinline__ void mma_bf16(float* d, const uint32_t* a, const uint32_t* b) {
    asm volatile(
        "mma.sync.aligned.m16n8k16.row.col.f32.bf16.bf16.f32 "
        "{%0,%1,%2,%3}, {%4,%5,%6,%7}, {%8,%9}, {%0,%1,%2,%3};"
        : "+f"(d[0]), "+f"(d[1]), "+f"(d[2]), "+f"(d[3])
        : "r"(a[0]), "r"(a[1]), "r"(a[2]), "r"(a[3]), "r"(b[0]), "r"(b[1]));
}
__device__ __forceinline__ void cp_async16(uint32_t smem_addr, const void* gmem) {
    asm volatile("cp.async.cg.shared.global [%0], [%1], 16;"
                 :: "r"(smem_addr), "l"(gmem) : "memory");
}
__device__ __forceinline__ void cp_commit() {
    asm volatile("cp.async.commit_group;" ::: "memory");
}
__device__ __forceinline__ void cp_wait_all() {
    asm volatile("cp.async.wait_group 0;" ::: "memory");
}
#define SW128(off) ((off) ^ (((off) >> 3) & 0x70))

// ---------------------------------------------------------------------------
// Kernel 1 — projection GEMM; epilogue emits V fp32 and bf16 hi/lo cat
// buffers (Q pre-scaled by 1/sqrt(dk)).
// ---------------------------------------------------------------------------
__global__ __launch_bounds__(256)
void proj_kernel(const float* __restrict__ xq, const float* __restrict__ xk,
                 const float* __restrict__ xv,
                 const float* __restrict__ wq, const float* __restrict__ bq,
                 const float* __restrict__ wk, const float* __restrict__ bk,
                 const float* __restrict__ wv, const float* __restrict__ bv)
{
    constexpr int PBM = 128, PBN = 64, PBK = 16;
    __shared__ float As[PBK][PBM];
    __shared__ float Bs[PBK][PBN];

    const int z = blockIdx.z;
    const float* __restrict__ X    = (z == 0) ? xq : (z == 1) ? xk : xv;
    const float* __restrict__ W    = (z == 0) ? wq : (z == 1) ? wk : wv;
    const float* __restrict__ bias = (z == 0) ? bq : (z == 1) ? bk : bv;

    const int n0 = blockIdx.y * PBM;
    const int c0 = blockIdx.x * PBN;
    const int tid = threadIdx.x;
    const int tx = tid & 15;
    const int ty = tid >> 4;

    float acc[8][4];
    #pragma unroll
    for (int i = 0; i < 8; ++i)
        #pragma unroll
        for (int j = 0; j < 4; ++j) acc[i][j] = 0.0f;

    for (int k0 = 0; k0 < kDM; k0 += PBK) {
        #pragma unroll
        for (int r = 0; r < 2; ++r) {
            int f   = tid + r * 256;
            int row = f >> 2;
            int kk  = (f & 3) * 4;
            float4 v = *reinterpret_cast<const float4*>(X + (n0 + row) * kDM + k0 + kk);
            As[kk + 0][row] = v.x; As[kk + 1][row] = v.y;
            As[kk + 2][row] = v.z; As[kk + 3][row] = v.w;
        }
        {
            int n  = tid >> 2;
            int kk = (tid & 3) * 4;
            float4 v = *reinterpret_cast<const float4*>(W + (c0 + n) * kDM + k0 + kk);
            Bs[kk + 0][n] = v.x; Bs[kk + 1][n] = v.y;
            Bs[kk + 2][n] = v.z; Bs[kk + 3][n] = v.w;
        }
        __syncthreads();

        #pragma unroll
        for (int k = 0; k < PBK; ++k) {
            float4 a0 = *reinterpret_cast<const float4*>(&As[k][ty * 8]);
            float4 a1 = *reinterpret_cast<const float4*>(&As[k][ty * 8 + 4]);
            float4 bb = *reinterpret_cast<const float4*>(&Bs[k][tx * 4]);
            float a[8] = {a0.x, a0.y, a0.z, a0.w, a1.x, a1.y, a1.z, a1.w};
            float b[4] = {bb.x, bb.y, bb.z, bb.w};
            #pragma unroll
            for (int i = 0; i < 8; ++i)
                #pragma unroll
                for (int j = 0; j < 4; ++j)
                    acc[i][j] = fmaf(a[i], b[j], acc[i][j]);
        }
        __syncthreads();
    }

    #pragma unroll
    for (int i = 0; i < 8; ++i) {
        const int row = n0 + ty * 8 + i;
        const int bb  = row / kS;
        const int ss  = row % kS;
        #pragma unroll
        for (int j = 0; j < 4; ++j) {
            const int col = c0 + tx * 4 + j;
            const int h = col >> 5, d = col & 31;
            const int r = (bb * kH + h) * kS + ss;
            float val = acc[i][j] + bias[col];
            if (z == 2) {
                g_v[r * kDK + d] = val;
            } else {
                if (z == 0) val *= kScale;           // pre-scale Q
                __nv_bfloat16 hi = __float2bfloat16(val);
                __nv_bfloat16 lo = __float2bfloat16(val - __bfloat162float(hi));
                __nv_bfloat16* dst = (z == 0) ? g_qcat : g_kcat;
                dst[r * kKC + d]       = hi;
                dst[r * kKC + 32 + d]  = lo;
            }
        }
    }
}

// ---------------------------------------------------------------------------
// Kernel 2 — score GEMM on mma.sync bf16 (hi/lo split, fp32 accumulate).
// S = Qhi.Khi + Qlo.Khi + Qhi.Klo (lo.lo dropped, <=2^-16 rel).
// Each CTA: one 128-row A tile (staged once), kJL=4 j-tiles with
// double-buffered cp.async B staging overlapped with MMA + epilogue.
// 8 warps as 4(m) x 2(n); warp tile 32x64; dense score store + tilemax.
// ---------------------------------------------------------------------------
__global__ __launch_bounds__(256, 2)
void score_gemm_tc(void)
{
    extern __shared__ __align__(128) char smem[];
    char* const sA = smem;                       // 16 KB
    char* const sB0 = smem + kTileB;             // 16 KB
    char* const sB1 = smem + 2 * kTileB;         // 16 KB

    const int bh = blockIdx.z;
    const int i0 = blockIdx.y * 128;
    const int jg = blockIdx.x;                   // j-group (4 tiles)
    const int tid  = threadIdx.x;
    const int wid  = tid >> 5;
    const int lane = tid & 31;

    const uint32_t sAu  = smem_u32(sA);
    const uint32_t sBu[2] = {smem_u32(sB0), smem_u32(sB1)};

    const uint4* __restrict__ Ag = reinterpret_cast<const uint4*>(
        g_qcat + ((size_t)bh * kS + i0) * kKC);
    const uint4* __restrict__ Kg = reinterpret_cast<const uint4*>(
        g_kcat + (size_t)bh * kS * kKC);

    // Initial stage: A + B(tile 0) via cp.async
    #pragma unroll
    for (int r = 0; r < 4; ++r) {
        const int f   = tid + r * 256;
        const int row = f >> 3;
        const int c16 = f & 7;
        const uint32_t off = SW128((uint32_t)(row * 128 + c16 * 16));
        cp_async16(sAu + off, Ag + row * 8 + c16);
        cp_async16(sBu[0] + off, Kg + (size_t)(jg * kJL * 128 + row) * 8 + c16);
    }
    cp_commit();
    cp_wait_all();
    __syncthreads();

    const int wm = wid & 3;            // 4 warps cover 128 rows
    const int wn = wid >> 2;           // 2 warps cover 128 cols
    const int imb = wm * 32;
    const int jnb = wn * 64;
    const int g  = lane >> 2;
    const int tg = lane & 3;

    #pragma unroll 1
    for (int jt = 0; jt < kJL; ++jt) {
        const int cur = jt & 1;
        const int j0 = (jg * kJL + jt) * 128;

        // Prefetch next B tile into the other buffer (overlaps with compute)
        if (jt + 1 < kJL) {
            #pragma unroll
            for (int r = 0; r < 4; ++r) {
                const int f   = tid + r * 256;
                const int row = f >> 3;
                const int c16 = f & 7;
                const uint32_t off = SW128((uint32_t)(row * 128 + c16 * 16));
                cp_async16(sBu[cur ^ 1] + off,
                           Kg + (size_t)(j0 + 128 + row) * 8 + c16);
            }
            cp_commit();
        }

        float acc[2][8][4];
        #pragma unroll
        for (int mt = 0; mt < 2; ++mt)
            #pragma unroll
            for (int nt = 0; nt < 8; ++nt)
                #pragma unroll
                for (int e = 0; e < 4; ++e) acc[mt][nt][e] = 0.0f;

        // Fragment-reuse mainloop: kk in {0,16}; A hi at kk, A lo at kk+32.
        #pragma unroll
        for (int kk = 0; kk < 32; kk += 16) {
            uint32_t afh[2][4], afl[2][4];
            #pragma unroll
            for (int mt = 0; mt < 2; ++mt) {
                const int row = imb + mt * 16 + (lane & 15);
                const int chkh = (kk >> 3) + (lane >> 4);
                const int chkl = ((kk + 32) >> 3) + (lane >> 4);
                ldsm_x4(afh[mt], sAu + SW128((uint32_t)(row * 128 + chkh * 16)));
                ldsm_x4(afl[mt], sAu + SW128((uint32_t)(row * 128 + chkl * 16)));
            }
            #pragma unroll
            for (int half = 0; half < 2; ++half) {
                uint32_t bfh[4][2], bfl[4][2];
                #pragma unroll
                for (int np = 0; np < 2; ++np) {
                    const int row = jnb + half * 32 + np * 16
                                  + (lane & 7) + ((lane & 16) >> 1);
                    const int chkh = (kk >> 3) + ((lane >> 3) & 1);
                    const int chkl = ((kk + 32) >> 3) + ((lane >> 3) & 1);
                    uint32_t r4[4];
                    ldsm_x4(r4, sBu[cur] + SW128((uint32_t)(row * 128 + chkh * 16)));
                    bfh[np * 2 + 0][0] = r4[0]; bfh[np * 2 + 0][1] = r4[1];
                    bfh[np * 2 + 1][0] = r4[2]; bfh[np * 2 + 1][1] = r4[3];
                    ldsm_x4(r4, sBu[cur] + SW128((uint32_t)(row * 128 + chkl * 16)));
                    bfl[np * 2 + 0][0] = r4[0]; bfl[np * 2 + 0][1] = r4[1];
                    bfl[np * 2 + 1][0] = r4[2]; bfl[np * 2 + 1][1] = r4[3];
                }
                #pragma unroll
                for (int mt = 0; mt < 2; ++mt)
                    #pragma unroll
                    for (int nt4 = 0; nt4 < 4; ++nt4) {
                        float* a = acc[mt][half * 4 + nt4];
                        mma_bf16(a, afh[mt], bfh[nt4]);   // hi.hi
                        mma_bf16(a, afl[mt], bfh[nt4]);   // lo.hi
                        mma_bf16(a, afh[mt], bfl[nt4]);   // hi.lo
                    }
            }
        }

        // Epilogue: store scores + per-tile row maxes (2 gmem slots per tile)
        float2* __restrict__ Sbase = reinterpret_cast<float2*>(
            g_s + ((size_t)bh * kS + i0) * kS + j0);
        const int jtile = jg * kJL + jt;

        #pragma unroll
        for (int mt = 0; mt < 2; ++mt) {
            const int r0 = imb + mt * 16 + g;
            float rm0 = -FLT_MAX, rm1 = -FLT_MAX;
            #pragma unroll
            for (int nt = 0; nt < 8; ++nt) {
                const int c2 = (jnb + nt * 8 + tg * 2) >> 1;
                float2 lo = make_float2(acc[mt][nt][0], acc[mt][nt][1]);
                float2 hi = make_float2(acc[mt][nt][2], acc[mt][nt][3]);
                Sbase[(size_t)r0 * (kS / 2) + c2]       = lo;
                Sbase[(size_t)(r0 + 8) * (kS / 2) + c2] = hi;
                rm0 = fmaxf(rm0, fmaxf(lo.x, lo.y));
                rm1 = fmaxf(rm1, fmaxf(hi.x, hi.y));
            }
            rm0 = fmaxf(rm0, __shfl_xor_sync(0xffffffffu, rm0, 1));
            rm0 = fmaxf(rm0, __shfl_xor_sync(0xffffffffu, rm0, 2));
            rm1 = fmaxf(rm1, __shfl_xor_sync(0xffffffffu, rm1, 1));
            rm1 = fmaxf(rm1, __shfl_xor_sync(0xffffffffu, rm1, 2));
            if (tg == 0) {
                const size_t rowg = (size_t)bh * kS + i0 + r0;
                g_tmax2[(rowg * kNT + jtile) * 2 + wn]       = rm0;
                g_tmax2[((rowg + 8) * kNT + jtile) * 2 + wn] = rm1;
            }
        }

        if (jt + 1 < kJL) cp_wait_all();
        __syncthreads();
    }
}

// ---------------------------------------------------------------------------
// Exact slow fallback for a row whose candidate list overflowed (rare):
// reads the DENSE stored scores (cheap), Michelot + ballot-pop AV.
// ---------------------------------------------------------------------------
__device__ __noinline__ float slow_row(const float4* __restrict__ S4,
                                       const float* __restrict__ Vbh,
                                       float thr, int lane)
{
    float tau = thr;
    int prev = -1;
    for (int it = 0; it < 200; ++it) {
        float sum = 0.0f; int cnt = 0;
        for (int c = lane; c < kS / 4; c += 32) {
            float4 v = __ldg(S4 + c);
            if (v.x > tau) { sum += v.x; ++cnt; }
            if (v.y > tau) { sum += v.y; ++cnt; }
            if (v.z > tau) { sum += v.z; ++cnt; }
            if (v.w > tau) { sum += v.w; ++cnt; }
        }
        #pragma unroll
        for (int o = 16; o; o >>= 1) {
            sum += __shfl_xor_sync(0xffffffffu, sum, o);
            cnt += __shfl_xor_sync(0xffffffffu, cnt, o);
        }
        if (cnt == prev || cnt == 0) break;
        tau = (sum - 1.0f) / (float)cnt;
        prev = cnt;
    }
    float a = 0.0f;
    for (int c = lane; c < kS / 4; c += 32) {
        float4 v = __ldg(S4 + c);
        const float vv[4] = {v.x, v.y, v.z, v.w};
        #pragma unroll
        for (int e = 0; e < 4; ++e) {
            float w = vv[e] - tau;
            unsigned mk = __ballot_sync(0xffffffffu, w > 0.0f);
            while (mk) {
                int b = __ffs(mk) - 1;
                mk &= mk - 1;
                float wb = __shfl_sync(0xffffffffu, w, b);
                int jj = __shfl_sync(0xffffffffu, c * 4 + e, b);
                a = fmaf(wb, __ldg(Vbh + jj * kDK + lane), a);
            }
        }
    }
    return a;
}

// ---------------------------------------------------------------------------
// Kernel 3 — sparsemax + AV, tile-selective. 1 warp per query row.
// Reads 16x2 tilemax slots -> exact row max -> scans only hot tiles.
// ---------------------------------------------------------------------------
__global__ __launch_bounds__(256, 2)
void sparsemax_av(float* __restrict__ out)
{
    __shared__ float2 Lists[8][kCap];

    const int bh   = blockIdx.y;
    const int warp = threadIdx.x >> 5;
    const int lane = threadIdx.x & 31;
    const unsigned lmask = (1u << lane) - 1u;
    const int qi   = blockIdx.x * 8 + warp;
    const size_t rowg = (size_t)bh * kS + qi;

    const float4* __restrict__ S4 =
        reinterpret_cast<const float4*>(g_s + rowg * kS);
    const float* __restrict__ Vbh = g_v + bh * kS * kDK;

    // Row max from the 16 tile maxes (2 slots each; exact)
    float tm = -FLT_MAX;
    if (lane < kNT) {
        const float t0 = __ldg(g_tmax2 + (rowg * kNT + lane) * 2);
        const float t1 = __ldg(g_tmax2 + (rowg * kNT + lane) * 2 + 1);
        tm = fmaxf(t0, t1);
    }
    float m = tm;
    #pragma unroll
    for (int o = 16; o; o >>= 1)
        m = fmaxf(m, __shfl_xor_sync(0xffffffffu, m, o));
    const float thr = m - 1.0f;
    unsigned tmask = __ballot_sync(0xffffffffu, lane < kNT && tm > thr);

    // Candidate compaction over selected 128-col tiles only
    float2* __restrict__ Lq = Lists[warp];
    int n = 0;
    unsigned it = tmask;
    while (it && n <= kCap) {
        const int t = __ffs(it) - 1;
        it &= it - 1;
        float4 v = __ldg(S4 + t * 32 + lane);
        const int jb = t * 128 + lane * 4;
        const float vv[4] = {v.x, v.y, v.z, v.w};
        #pragma unroll
        for (int e = 0; e < 4; ++e) {
            const bool cand = vv[e] > thr;
            const unsigned mk = __ballot_sync(0xffffffffu, cand);
            if (mk) {
                const int idx = n + __popc(mk & lmask);
                if (cand && idx < kCap)
                    Lq[idx] = make_float2(vv[e], __int_as_float(jb + e));
                n += __popc(mk);
            }
        }
    }
    __syncwarp();

    float a;
    if (n <= kCap) {
        float c0 = (lane      < n) ? Lq[lane     ].x : -FLT_MAX;
        float c1 = (lane + 32 < n) ? Lq[lane + 32].x : -FLT_MAX;
        float c2 = (lane + 64 < n) ? Lq[lane + 64].x : -FLT_MAX;
        float c3 = (lane + 96 < n) ? Lq[lane + 96].x : -FLT_MAX;
        float tau = thr;
        int prev = -1;
        for (int iter = 0; iter < 80; ++iter) {
            float sum = 0.0f; int cnt = 0;
            if (c0 > tau) { sum += c0; ++cnt; }
            if (c1 > tau) { sum += c1; ++cnt; }
            if (c2 > tau) { sum += c2; ++cnt; }
            if (c3 > tau) { sum += c3; ++cnt; }
            #pragma unroll
            for (int o = 16; o; o >>= 1) {
                sum += __shfl_xor_sync(0xffffffffu, sum, o);
                cnt += __shfl_xor_sync(0xffffffffu, cnt, o);
            }
            if (cnt == prev || cnt == 0) break;
            tau = (sum - 1.0f) / (float)cnt;
            prev = cnt;
        }
        float a0 = 0.0f, a1 = 0.0f;
        int ci = 0;
        for (; ci + 2 <= n; ci += 2) {
            float2 p0 = Lq[ci], p1 = Lq[ci + 1];
            float w0 = fmaxf(p0.x - tau, 0.0f);
            float w1 = fmaxf(p1.x - tau, 0.0f);
            a0 = fmaf(w0, __ldg(Vbh + __float_as_int(p0.y) * kDK + lane), a0);
            a1 = fmaf(w1, __ldg(Vbh + __float_as_int(p1.y) * kDK + lane), a1);
        }
        if (ci < n) {
            float2 p = Lq[ci];
            float w = fmaxf(p.x - tau, 0.0f);
            a0 = fmaf(w, __ldg(Vbh + __float_as_int(p.y) * kDK + lane), a0);
        }
        a = a0 + a1;
    } else {
        a = slow_row(S4, Vbh, thr, lane);
    }

    const int bb = bh >> 3;
    const int h  = bh & 7;
    out[(bb * kS + qi) * kDM + h * kDK + lane] = a;
}

// ---------------------------------------------------------------------------
extern "C" void kernel_launch(void* const* d_in, const int* in_sizes, int n_in,
                              void* d_out, int out_size)
{
    const float* query = (const float*)d_in[0];
    const float* key   = (const float*)d_in[1];
    const float* value = (const float*)d_in[2];
    const float* Wq    = (const float*)d_in[3];
    const float* bq    = (const float*)d_in[4];
    const float* Wk    = (const float*)d_in[5];
    const float* bk    = (const float*)d_in[6];
    const float* Wv    = (const float*)d_in[7];
    const float* bv    = (const float*)d_in[8];
    float* out = (float*)d_out;

    dim3 pgrid(kDM / 64, kNRow / 128, 3);      // (4, 32, 3)
    proj_kernel<<<pgrid, 256>>>(query, key, value, Wq, bq, Wk, bk, Wv, bv);

    cudaFuncSetAttribute(score_gemm_tc,
                         cudaFuncAttributeMaxDynamicSharedMemorySize, kSmemScore);
    dim3 sgrid(kS / (128 * kJL), kS / 128, kB * kH);   // (4, 16, 16)
    score_gemm_tc<<<sgrid, 256, kSmemScore>>>();

    dim3 agrid(kS / 8, kB * kH);               // (256, 16)
    sparsemax_av<<<agrid, 256>>>(out);

    (void)in_sizes; (void)n_in; (void)out_size;
}